// round 14
// baseline (speedup 1.0000x reference)
#include <cuda_runtime.h>
#include <cuda_bf16.h>

// InternalCoordinateTransform — flat, smem-free, SINGLE kernel.
// z_mat row r = (r+3, r+2, r+1, r): row r reads atoms r..r+3 (floats
// 3r..3r+11), writes floats 3r+9..3r+11.
// Thread g handles rows 4g+1..4g+4 (R12 phase: BOTH x loads and stores are
// 16B-aligned vector ops):
//   x:      floats 12g..12g+23  -> 6 aligned LDG.128 (atoms 4g..4g+7)
//   out:    floats 12g+12..12g+23 -> 3 aligned STG.128
//   params: float4 at index g (rows 4g..4g+3; use .y.z.w) + 6 scalar LDG.32
//           at row 4g+4 (L1-resident; consecutive across warp). 1/sigma via
//           inline MUFU rcp (hidden under fma pipe).
// Head floats 0..8 + row 0 handled by the g==0 thread from registers.
// Grid is exact (2048*624 = 9984 * 128): no bounds check.
// Lessons: R4 no reg cap; R11 no smem block design (wave quantization);
// R13 never misalign the STORE path (5-store path cost +2.2us alu/L2).

#define NDIM    7500
#define NGROUPS 624
#define PI_F    3.14159265358979f
#define TWO_PI  6.28318530717959f

__device__ __forceinline__ float rsqrt_ap(float x) {
    float r; asm("rsqrt.approx.f32 %0, %1;" : "=f"(r) : "f"(x)); return r;
}
__device__ __forceinline__ float sqrt_ap(float x) {
    float r; asm("sqrt.approx.f32 %0, %1;" : "=f"(r) : "f"(x)); return r;
}
__device__ __forceinline__ float rcp_ap(float x) {
    float r; asm("rcp.approx.f32 %0, %1;" : "=f"(r) : "f"(x)); return r;
}

// Hastings-style acos, |err| ~1e-7 rad, x in [-1,1].
__device__ __forceinline__ float acos_fast(float x) {
    float xa = fabsf(x);
    float p = -0.0012624911f;
    p = fmaf(p, xa,  0.0066700901f);
    p = fmaf(p, xa, -0.0170881256f);
    p = fmaf(p, xa,  0.0308918810f);
    p = fmaf(p, xa, -0.0501743046f);
    p = fmaf(p, xa,  0.0889789874f);
    p = fmaf(p, xa, -0.2145988016f);
    p = fmaf(p, xa,  1.5707963050f);
    float r = sqrt_ap(1.0f - xa) * p;
    return (x >= 0.0f) ? r : (PI_F - r);
}

// Full-quadrant atan2, |err| ~ few e-6 rad.
__device__ __forceinline__ float atan2_fast(float y, float x) {
    float ax = fabsf(x), ay = fabsf(y);
    float mx = fmaxf(fmaxf(ax, ay), 1e-35f);
    float mn = fminf(ax, ay);
    float t  = mn * rcp_ap(mx);
    float s  = t * t;
    float p = -0.01172120f;
    p = fmaf(p, s,  0.05265332f);
    p = fmaf(p, s, -0.11643287f);
    p = fmaf(p, s,  0.19354346f);
    p = fmaf(p, s, -0.33262347f);
    p = fmaf(p, s,  0.99997726f);
    float r = t * p;
    if (ay > ax)   r = 1.57079632679f - r;
    if (x < 0.0f)  r = PI_F - r;
    return copysignf(r, y);
}

// One z-row from 12 consecutive floats:
// p3=a[0..2] (atom r), p2=a[3..5], p1=a[6..8], p4=a[9..11] (atom r+3)
__device__ __forceinline__ void ic_row(const float* a, float& bond, float& ang, float& dihe)
{
    float d21x = a[3]-a[6], d21y = a[4]-a[7], d21z = a[5]-a[8];
    float d41x = a[9]-a[6], d41y = a[10]-a[7], d41z = a[11]-a[8];
    float s21 = fmaf(d21x,d21x, fmaf(d21y,d21y, d21z*d21z));
    float s41 = fmaf(d41x,d41x, fmaf(d41y,d41y, d41z*d41z));
    float r21 = rsqrt_ap(s21), r41 = rsqrt_ap(s41);
    bond = s41 * r41;
    float dotc = fmaf(d21x,d41x, fmaf(d21y,d41y, d21z*d41z));
    float cosang = fminf(fmaxf(dotc*r21*r41, -1.0f), 1.0f);
    ang = acos_fast(cosang);
    float ux = d21x*r21, uy = d21y*r21, uz = d21z*r21;
    float b0x = a[0]-a[3], b0y = a[1]-a[4], b0z = a[2]-a[5];
    float db0 = fmaf(b0x,ux, fmaf(b0y,uy, b0z*uz));
    float vx = fmaf(-db0,ux,b0x), vy = fmaf(-db0,uy,b0y), vz = fmaf(-db0,uz,b0z);
    float db2 = fmaf(d41x,ux, fmaf(d41y,uy, d41z*uz));
    float wx = fmaf(-db2,ux,d41x), wy = fmaf(-db2,uy,d41y), wz = fmaf(-db2,uz,d41z);
    float xx = fmaf(vx,wx, fmaf(vy,wy, vz*wz));
    float cx = fmaf(uy,vz,-uz*vy), cy = fmaf(uz,vx,-ux*vz), cz = fmaf(ux,vy,-uy*vx);
    float yy = fmaf(cx,wx, fmaf(cy,wy, cz*wz));
    dihe = atan2_fast(yy, xx);
}

__device__ __forceinline__ void norm_row(float bond, float ang, float dihe,
                                         float mbv, float sbv, float mav, float sav,
                                         float mdv, float sdv,
                                         float& ob, float& oa, float& od)
{
    ob = (bond - mbv) * rcp_ap(sbv);
    oa = (ang  - mav) * rcp_ap(sav);
    float dd = dihe - mdv;
    dd = (dd < -PI_F) ? dd + TWO_PI : dd;
    dd = (dd >  PI_F) ? dd - TWO_PI : dd;
    od = dd * rcp_ap(sdv);
}

__global__ __launch_bounds__(128)
void ict_flat(const float* __restrict__ x,
              const float* __restrict__ mb, const float* __restrict__ sb,
              const float* __restrict__ ma, const float* __restrict__ sa,
              const float* __restrict__ md, const float* __restrict__ sd,
              float* __restrict__ out)
{
    unsigned t = blockIdx.x * 128u + threadIdx.x;   // grid exact: t < 2048*624
    unsigned b = t / NGROUPS;                        // constant divisor -> mulhi
    unsigned g = t - b * NGROUPS;
    const size_t base = (size_t)b * NDIM;

    const float4* __restrict__ xin  = (const float4*)(x + base);
    float4*       __restrict__ outv = (float4*)(out + base);

    // ---- x: floats 12g..12g+23 (atoms 4g..4g+7): 6 aligned LDG.128 ----
    float a[24];
#pragma unroll
    for (int q = 0; q < 6; q++) {
        float4 f = __ldg(xin + 3 * g + q);
        a[4*q] = f.x; a[4*q+1] = f.y; a[4*q+2] = f.z; a[4*q+3] = f.w;
    }

    // ---- params for rows 4g+1..4g+4: f4 at g (.y.z.w) + scalar at 4g+4 ----
    float4 qmb = __ldg((const float4*)mb + g);
    float4 qsb = __ldg((const float4*)sb + g);
    float4 qma = __ldg((const float4*)ma + g);
    float4 qsa = __ldg((const float4*)sa + g);
    float4 qmd = __ldg((const float4*)md + g);
    float4 qsd = __ldg((const float4*)sd + g);
    int r4 = 4 * g + 4;                               // <= 2496, in-bounds
    float pmb[4] = {qmb.y, qmb.z, qmb.w, __ldg(mb + r4)};
    float psb[4] = {qsb.y, qsb.z, qsb.w, __ldg(sb + r4)};
    float pma[4] = {qma.y, qma.z, qma.w, __ldg(ma + r4)};
    float psa[4] = {qsa.y, qsa.z, qsa.w, __ldg(sa + r4)};
    float pmd[4] = {qmd.y, qmd.z, qmd.w, __ldg(md + r4)};
    float psd[4] = {qsd.y, qsd.z, qsd.w, __ldg(sd + r4)};

    float res[12];
#pragma unroll
    for (int j = 0; j < 4; j++) {
        // row r = 4g+1+j: atoms r..r+3 start at local float 3*(1+j)
        float bond, ang, dihe;
        ic_row(a + 3 * (1 + j), bond, ang, dihe);
        norm_row(bond, ang, dihe, pmb[j], psb[j], pma[j], psa[j], pmd[j], psd[j],
                 res[3*j], res[3*j+1], res[3*j+2]);
    }

    // ---- stores: floats 12g+12..12g+23 = f4 3g+3..3g+5, all aligned ----
    outv[3*g + 3] = make_float4(res[0], res[1], res[2],  res[3]);
    outv[3*g + 4] = make_float4(res[4], res[5], res[6],  res[7]);
    outv[3*g + 5] = make_float4(res[8], res[9], res[10], res[11]);

    // ---- g==0: head floats 0..8 + row 0 (atoms 0..3 = a[0..11]) ----
    if (g == 0) {
        float bond, ang, dihe;
        ic_row(a, bond, ang, dihe);
        float ob, oa, od;
        norm_row(bond, ang, dihe,
                 qmb.x, qsb.x, qma.x, qsa.x, qmd.x, qsd.x, ob, oa, od);
        outv[0] = make_float4(a[0], a[1], a[2], a[3]);
        outv[1] = make_float4(a[4], a[5], a[6], a[7]);
        outv[2] = make_float4(a[8], ob, oa, od);
    }
}

extern "C" void kernel_launch(void* const* d_in, const int* in_sizes, int n_in,
                              void* d_out, int out_size)
{
    const float* x  = (const float*)d_in[0];
    const float* mb = (const float*)d_in[2];
    const float* sb = (const float*)d_in[3];
    const float* ma = (const float*)d_in[4];
    const float* sa = (const float*)d_in[5];
    const float* md = (const float*)d_in[6];
    const float* sd = (const float*)d_in[7];

    int bsz   = in_sizes[0] / NDIM;          // 2048
    int total = bsz * NGROUPS;               // 1,277,952 = 9984 * 128 exactly

    ict_flat<<<total / 128, 128>>>(x, mb, sb, ma, sa, md, sd, (float*)d_out);
}

// round 15
// speedup vs baseline: 1.0678x; 1.0678x over previous
#include <cuda_runtime.h>
#include <cuda_bf16.h>

// InternalCoordinateTransform — flat grid + prep-packed params (R12 base)
// with shared bond-vector geometry, restructured for ILP (no serial chain).
// z_mat row r = (r+3, r+2, r+1, r): row r reads atoms r..r+3, writes floats
// 3r+9..3r+11. Thread (b,g) handles rows 4g+1..4g+4:
//   x:   floats 12g..12g+23 -> 6 aligned LDG.128 (atoms 4g..4g+7)
//   out: floats 12g+12..12g+23 -> 3 aligned STG.128
//   params: prep-packed group-SoA float4 (6 LDG.128; measured cheapest path)
// Geometry: e_k = atom(4g+k+1)-atom(4g+k), k=1..6 (18 subs, shared);
// S_k=|e_k|^2, R_k=rsqrt(S_k) (k=2..6), D_k=e_k.e_{k+1} (k=1..5) ALL
// computed upfront with no cross-dependencies (R8's win without its serial
// Rc/Dp chain that killed issue%). Then 4 independent row tails.
// Lessons: R4 no reg cap; R11 no smem block design; R13 aligned stores;
// R14 no inline scalar param loads.

#define NDIM    7500
#define NGROUPS 624
#define PI_F    3.14159265358979f
#define TWO_PI  6.28318530717959f

__device__ float4 g_prm[6 * NGROUPS];  // {isb},{-mb*isb},{isa},{-ma*isa},{md},{isd}

__device__ __forceinline__ float rsqrt_ap(float x) {
    float r; asm("rsqrt.approx.f32 %0, %1;" : "=f"(r) : "f"(x)); return r;
}
__device__ __forceinline__ float sqrt_ap(float x) {
    float r; asm("sqrt.approx.f32 %0, %1;" : "=f"(r) : "f"(x)); return r;
}
__device__ __forceinline__ float rcp_ap(float x) {
    float r; asm("rcp.approx.f32 %0, %1;" : "=f"(r) : "f"(x)); return r;
}

// Hastings-style acos, |err| ~1e-7 rad, x in [-1,1].
__device__ __forceinline__ float acos_fast(float x) {
    float xa = fabsf(x);
    float p = -0.0012624911f;
    p = fmaf(p, xa,  0.0066700901f);
    p = fmaf(p, xa, -0.0170881256f);
    p = fmaf(p, xa,  0.0308918810f);
    p = fmaf(p, xa, -0.0501743046f);
    p = fmaf(p, xa,  0.0889789874f);
    p = fmaf(p, xa, -0.2145988016f);
    p = fmaf(p, xa,  1.5707963050f);
    float r = sqrt_ap(1.0f - xa) * p;
    return (x >= 0.0f) ? r : (PI_F - r);
}

// Full-quadrant atan2, |err| ~ few e-6 rad.
__device__ __forceinline__ float atan2_fast(float y, float x) {
    float ax = fabsf(x), ay = fabsf(y);
    float mx = fmaxf(fmaxf(ax, ay), 1e-35f);
    float mn = fminf(ax, ay);
    float t  = mn * rcp_ap(mx);
    float s  = t * t;
    float p = -0.01172120f;
    p = fmaf(p, s,  0.05265332f);
    p = fmaf(p, s, -0.11643287f);
    p = fmaf(p, s,  0.19354346f);
    p = fmaf(p, s, -0.33262347f);
    p = fmaf(p, s,  0.99997726f);
    float r = t * p;
    if (ay > ax)   r = 1.57079632679f - r;
    if (x < 0.0f)  r = PI_F - r;
    return copysignf(r, y);
}

// Generic row (row 0 only): p3=a[0..2], p2=a[3..5], p1=a[6..8], p4=a[9..11]
__device__ __forceinline__ void ic_row(const float* a, float& bond, float& ang, float& dihe)
{
    float d21x = a[3]-a[6], d21y = a[4]-a[7], d21z = a[5]-a[8];
    float d41x = a[9]-a[6], d41y = a[10]-a[7], d41z = a[11]-a[8];
    float s21 = fmaf(d21x,d21x, fmaf(d21y,d21y, d21z*d21z));
    float s41 = fmaf(d41x,d41x, fmaf(d41y,d41y, d41z*d41z));
    float r21 = rsqrt_ap(s21), r41 = rsqrt_ap(s41);
    bond = s41 * r41;
    float dotc = fmaf(d21x,d41x, fmaf(d21y,d41y, d21z*d41z));
    float cosang = fminf(fmaxf(dotc*r21*r41, -1.0f), 1.0f);
    ang = acos_fast(cosang);
    float ux = d21x*r21, uy = d21y*r21, uz = d21z*r21;
    float b0x = a[0]-a[3], b0y = a[1]-a[4], b0z = a[2]-a[5];
    float db0 = fmaf(b0x,ux, fmaf(b0y,uy, b0z*uz));
    float vx = fmaf(-db0,ux,b0x), vy = fmaf(-db0,uy,b0y), vz = fmaf(-db0,uz,b0z);
    float db2 = fmaf(d41x,ux, fmaf(d41y,uy, d41z*uz));
    float wx = fmaf(-db2,ux,d41x), wy = fmaf(-db2,uy,d41y), wz = fmaf(-db2,uz,d41z);
    float xx = fmaf(vx,wx, fmaf(vy,wy, vz*wz));
    float cx = fmaf(uy,vz,-uz*vy), cy = fmaf(uz,vx,-ux*vz), cz = fmaf(ux,vy,-uy*vx);
    float yy = fmaf(cx,wx, fmaf(cy,wy, cz*wz));
    dihe = atan2_fast(yy, xx);
}

__global__ void prep_kernel(const float* __restrict__ mb, const float* __restrict__ sb,
                            const float* __restrict__ ma, const float* __restrict__ sa,
                            const float* __restrict__ md, const float* __restrict__ sd)
{
    int g = blockIdx.x * blockDim.x + threadIdx.x;
    if (g >= NGROUPS) return;
    float4 v0, v1, v2, v3, v4, v5;
    float* p0 = (float*)&v0; float* p1 = (float*)&v1; float* p2 = (float*)&v2;
    float* p3 = (float*)&v3; float* p4 = (float*)&v4; float* p5 = (float*)&v5;
#pragma unroll
    for (int j = 0; j < 4; j++) {
        int r = 4 * g + 1 + j;
        float isb = rcp_ap(sb[r]);
        float isa = rcp_ap(sa[r]);
        float isd = rcp_ap(sd[r]);
        p0[j] = isb;   p1[j] = -mb[r] * isb;
        p2[j] = isa;   p3[j] = -ma[r] * isa;
        p4[j] = md[r]; p5[j] = isd;
    }
    g_prm[0 * NGROUPS + g] = v0;
    g_prm[1 * NGROUPS + g] = v1;
    g_prm[2 * NGROUPS + g] = v2;
    g_prm[3 * NGROUPS + g] = v3;
    g_prm[4 * NGROUPS + g] = v4;
    g_prm[5 * NGROUPS + g] = v5;
}

__global__ __launch_bounds__(128)
void ict_flat(const float* __restrict__ x,
              const float* __restrict__ mb, const float* __restrict__ sb,
              const float* __restrict__ ma, const float* __restrict__ sa,
              const float* __restrict__ md, const float* __restrict__ sd,
              float* __restrict__ out)
{
    int g = blockIdx.x * 128 + threadIdx.x;
    if (g >= NGROUPS) return;
    const size_t base = (size_t)blockIdx.y * NDIM;

    const float4* __restrict__ xin  = (const float4*)(x + base);
    float4*       __restrict__ outv = (float4*)(out + base);

    // ---- x: floats 12g..12g+23 (atoms 4g..4g+7): 6 aligned LDG.128 ----
    float4 f0 = __ldg(xin + 3*g);
    float4 f1 = __ldg(xin + 3*g + 1);
    float4 f2 = __ldg(xin + 3*g + 2);
    float4 f3 = __ldg(xin + 3*g + 3);
    float4 f4 = __ldg(xin + 3*g + 4);
    float4 f5 = __ldg(xin + 3*g + 5);

    // ---- shared bond vectors e_k = atom(4g+k+1)-atom(4g+k), k=1..6 ----
    float ex[7], ey[7], ez[7];
    ex[1] = f1.z - f0.w; ey[1] = f1.w - f1.x; ez[1] = f2.x - f1.y;
    ex[2] = f2.y - f1.z; ey[2] = f2.z - f1.w; ez[2] = f2.w - f2.x;
    ex[3] = f3.x - f2.y; ey[3] = f3.y - f2.z; ez[3] = f3.z - f2.w;
    ex[4] = f3.w - f3.x; ey[4] = f4.x - f3.y; ez[4] = f4.y - f3.z;
    ex[5] = f4.z - f3.w; ey[5] = f4.w - f4.x; ez[5] = f5.x - f4.y;
    ex[6] = f5.y - f4.z; ey[6] = f5.z - f4.w; ez[6] = f5.w - f5.x;

    // ---- upfront parallel shared terms (NO cross-dependencies) ----
    float S[7], R[7], D[6];
#pragma unroll
    for (int k = 2; k <= 6; k++) {
        S[k] = fmaf(ex[k],ex[k], fmaf(ey[k],ey[k], ez[k]*ez[k]));
        R[k] = rsqrt_ap(S[k]);
    }
#pragma unroll
    for (int k = 1; k <= 5; k++)
        D[k] = fmaf(ex[k],ex[k+1], fmaf(ey[k],ey[k+1], ez[k]*ez[k+1]));

    // ---- packed params (6 aligned LDG.128, L2-resident) ----
    float4 c0 = g_prm[0 * NGROUPS + g];
    float4 c1 = g_prm[1 * NGROUPS + g];
    float4 c2 = g_prm[2 * NGROUPS + g];
    float4 c3 = g_prm[3 * NGROUPS + g];
    float4 c4 = g_prm[4 * NGROUPS + g];
    float4 c5 = g_prm[5 * NGROUPS + g];
    const float* pc0 = (const float*)&c0; const float* pc1 = (const float*)&c1;
    const float* pc2 = (const float*)&c2; const float* pc3 = (const float*)&c3;
    const float* pc4 = (const float*)&c4; const float* pc5 = (const float*)&c5;

    // ---- 4 independent row tails (row r = 4g+j, j=1..4) ----
    float res[12];
#pragma unroll
    for (int j = 1; j <= 4; j++) {
        float bond = S[j+2] * R[j+2];

        float cosang = fminf(fmaxf(-D[j+1] * R[j+1] * R[j+2], -1.0f), 1.0f);
        float ang = acos_fast(cosang);

        float inv = R[j+1] * R[j+1];         // 1/S_{j+1}
        float fa = D[j]   * inv;
        float fb = D[j+1] * inv;
        // v' = e_j - fa*e_{j+1} (true v = -v');  w = e_{j+2} - fb*e_{j+1}
        float vx = fmaf(-fa, ex[j+1], ex[j]);
        float vy = fmaf(-fa, ey[j+1], ey[j]);
        float vz = fmaf(-fa, ez[j+1], ez[j]);
        float wx = fmaf(-fb, ex[j+1], ex[j+2]);
        float wy = fmaf(-fb, ey[j+1], ey[j+2]);
        float wz = fmaf(-fb, ez[j+1], ez[j+2]);

        float xx = -fmaf(vx,wx, fmaf(vy,wy, vz*wz));
        float cxx = fmaf(ey[j+1],vz, -ez[j+1]*vy);
        float cyy = fmaf(ez[j+1],vx, -ex[j+1]*vz);
        float czz = fmaf(ex[j+1],vy, -ey[j+1]*vx);
        float yy = R[j+1] * fmaf(cxx,wx, fmaf(cyy,wy, czz*wz));
        float dihe = atan2_fast(yy, xx);

        res[3*(j-1)]   = fmaf(bond, pc0[j-1], pc1[j-1]);
        res[3*(j-1)+1] = fmaf(ang,  pc2[j-1], pc3[j-1]);
        float dd = dihe - pc4[j-1];
        dd = (dd < -PI_F) ? dd + TWO_PI : dd;
        dd = (dd >  PI_F) ? dd - TWO_PI : dd;
        res[3*(j-1)+2] = dd * pc5[j-1];
    }

    // ---- stores: floats 12g+12..12g+23 = f4 3g+3..3g+5, all aligned ----
    outv[3*g + 3] = make_float4(res[0], res[1], res[2],  res[3]);
    outv[3*g + 4] = make_float4(res[4], res[5], res[6],  res[7]);
    outv[3*g + 5] = make_float4(res[8], res[9], res[10], res[11]);

    // ---- g==0: head floats 0..8 + row 0 (atoms 0..3) ----
    if (g == 0) {
        float a0[12] = {f0.x, f0.y, f0.z, f0.w, f1.x, f1.y,
                        f1.z, f1.w, f2.x, f2.y, f2.z, f2.w};
        float bond, ang, dihe;
        ic_row(a0, bond, ang, dihe);
        float ob = (bond - __ldg(mb)) * rcp_ap(__ldg(sb));
        float oa = (ang  - __ldg(ma)) * rcp_ap(__ldg(sa));
        float dd = dihe - __ldg(md);
        dd = (dd < -PI_F) ? dd + TWO_PI : dd;
        dd = (dd >  PI_F) ? dd - TWO_PI : dd;
        float od = dd * rcp_ap(__ldg(sd));
        outv[0] = make_float4(a0[0], a0[1], a0[2], a0[3]);
        outv[1] = make_float4(a0[4], a0[5], a0[6], a0[7]);
        outv[2] = make_float4(a0[8], ob, oa, od);
    }
}

extern "C" void kernel_launch(void* const* d_in, const int* in_sizes, int n_in,
                              void* d_out, int out_size)
{
    const float* x  = (const float*)d_in[0];
    const float* mb = (const float*)d_in[2];
    const float* sb = (const float*)d_in[3];
    const float* ma = (const float*)d_in[4];
    const float* sa = (const float*)d_in[5];
    const float* md = (const float*)d_in[6];
    const float* sd = (const float*)d_in[7];

    int bsz = in_sizes[0] / NDIM;                 // 2048

    prep_kernel<<<(NGROUPS + 255) / 256, 256>>>(mb, sb, ma, sa, md, sd);
    dim3 grid((NGROUPS + 127) / 128, bsz);        // (5, 2048)
    ict_flat<<<grid, 128>>>(x, mb, sb, ma, sa, md, sd, (float*)d_out);
}